// round 11
// baseline (speedup 1.0000x reference)
#include <cuda_runtime.h>
#include <cuda_bf16.h>
#include <mma.h>
#include <cstdint>
#include <cstddef>

using namespace nvcuda;

#define NN 100000
#define NE 3200000

// ---------------- device scratch ----------------
__device__ int   g_rowptr[NN + 1];
__device__ int   g_cursor[NN];
__device__ int   g_col[NE];
__device__ float g_z0[(size_t)NN * 256];   // bf16 hi/lo planes (raw bytes)
__device__ float g_z1[(size_t)NN * 256];   // bf16 hi/lo planes
__device__ float g_hb[(size_t)NN * 256];   // fp32
__device__ float g_s[768];
__device__ float g_t[768];
__device__ float g_wc[514];                // fused W2@outW [256x2] + bias[2]
__device__ __nv_bfloat16 g_wh[5 * 65536];  // weight hi images (L0W1,L0W2,L1W1,L1W2,L2W1)
__device__ __nv_bfloat16 g_wl[5 * 65536];  // weight lo images

// ---------------- helpers ----------------
__device__ __forceinline__ uint32_t smem_cast(const void* p) {
    return (uint32_t)__cvta_generic_to_shared(p);
}
#define CP16(d, s) asm volatile("cp.async.ca.shared.global [%0], [%1], 16;" :: "r"(d), "l"(s))
#define CP_COMMIT() asm volatile("cp.async.commit_group;" ::: "memory")
#define CP_WAIT0() asm volatile("cp.async.wait_group 0;" ::: "memory")

// bf16 planar packing: low 16 bits of a word = even element, high 16 = odd element
__device__ __forceinline__ float blo(uint32_t w) { return __uint_as_float(w << 16); }
__device__ __forceinline__ float bhi(uint32_t w) { return __uint_as_float(w & 0xffff0000u); }
__device__ __forceinline__ uint32_t pack_hi(float a, float b) {  // truncation
    return (__float_as_uint(a) >> 16) | (__float_as_uint(b) & 0xffff0000u);
}
__device__ __forceinline__ uint32_t pack_lo(float a, float b) {  // RN residuals
    float ra = a - __uint_as_float(__float_as_uint(a) & 0xffff0000u);
    float rb = b - __uint_as_float(__float_as_uint(b) & 0xffff0000u);
    __nv_bfloat162 p = __floats2bfloat162_rn(ra, rb);
    return *(uint32_t*)&p;
}

// ---------------- CSR build ----------------
__global__ void k_count(const int* __restrict__ dst) {
    int e = blockIdx.x * blockDim.x + threadIdx.x;
    if (e < NE) atomicAdd(&g_cursor[dst[e]], 1);
}
__global__ void k_scan() {
    __shared__ int wsum[32];
    __shared__ int s_carry;
    int tid = threadIdx.x, lane = tid & 31, wid = tid >> 5;
    if (tid == 0) s_carry = 0;
    __syncthreads();
    for (int base = 0; base < NN; base += 1024) {
        int i = base + tid;
        int v = (i < NN) ? g_cursor[i] : 0;
        int x = v;
#pragma unroll
        for (int off = 1; off < 32; off <<= 1) {
            int y = __shfl_up_sync(0xffffffffu, x, off);
            if (lane >= off) x += y;
        }
        if (lane == 31) wsum[wid] = x;
        __syncthreads();
        if (wid == 0) {
            int w = wsum[lane];
#pragma unroll
            for (int off = 1; off < 32; off <<= 1) {
                int y = __shfl_up_sync(0xffffffffu, w, off);
                if (lane >= off) w += y;
            }
            wsum[lane] = w;
        }
        __syncthreads();
        int incl = x + (wid ? wsum[wid - 1] : 0) + s_carry;
        if (i < NN) {
            g_rowptr[i + 1] = incl;
            g_cursor[i] = incl - v;
        }
        __syncthreads();
        if (tid == 1023) s_carry = incl;
        __syncthreads();
    }
    if (tid == 0) g_rowptr[0] = 0;
}
__global__ void k_fill(const int* __restrict__ ei) {
    int e = blockIdx.x * blockDim.x + threadIdx.x;
    if (e < NE) {
        int s = ei[e];
        int d = ei[NE + e];
        int p = atomicAdd(&g_cursor[d], 1);
        g_col[p] = s;
    }
}

// ---------------- agg (F=128, fp32 in, planes out) ----------------
__global__ void k_agg1(const float* __restrict__ h,
                       __nv_bfloat16* __restrict__ OH, __nv_bfloat16* __restrict__ OL) {
    int w = (blockIdx.x * blockDim.x + threadIdx.x) >> 5;
    if (w >= NN) return;
    int lane = threadIdx.x & 31;
    const float4* hv = (const float4*)h;
    float4 acc = hv[(size_t)w * 32 + lane];
    int e = g_rowptr[w], end = g_rowptr[w + 1];
    for (; e + 1 < end; e += 2) {
        float4 t0 = __ldg(hv + (size_t)g_col[e] * 32 + lane);
        float4 t1 = __ldg(hv + (size_t)g_col[e + 1] * 32 + lane);
        acc.x += t0.x + t1.x; acc.y += t0.y + t1.y;
        acc.z += t0.z + t1.z; acc.w += t0.w + t1.w;
    }
    if (e < end) {
        float4 t0 = __ldg(hv + (size_t)g_col[e] * 32 + lane);
        acc.x += t0.x; acc.y += t0.y; acc.z += t0.z; acc.w += t0.w;
    }
    uint2 hw = make_uint2(pack_hi(acc.x, acc.y), pack_hi(acc.z, acc.w));
    uint2 lw = make_uint2(pack_lo(acc.x, acc.y), pack_lo(acc.z, acc.w));
    ((uint2*)OH)[(size_t)w * 32 + lane] = hw;
    ((uint2*)OL)[(size_t)w * 32 + lane] = lw;
}

// ---------------- agg (F=256, fp32 in, planes out) ----------------
__global__ void k_agg2(const float* __restrict__ h,
                       __nv_bfloat16* __restrict__ OH, __nv_bfloat16* __restrict__ OL) {
    int w = (blockIdx.x * blockDim.x + threadIdx.x) >> 5;
    if (w >= NN) return;
    int lane = threadIdx.x & 31;
    const float4* hv = (const float4*)h;
    float4 acc[2];
#pragma unroll
    for (int v = 0; v < 2; v++) acc[v] = hv[(size_t)w * 64 + v * 32 + lane];
    int e = g_rowptr[w], end = g_rowptr[w + 1];
    for (; e + 1 < end; e += 2) {
        const float4* p0 = hv + (size_t)g_col[e] * 64;
        const float4* p1 = hv + (size_t)g_col[e + 1] * 64;
        float4 t0[2], t1[2];
#pragma unroll
        for (int v = 0; v < 2; v++) {
            t0[v] = __ldg(p0 + v * 32 + lane);
            t1[v] = __ldg(p1 + v * 32 + lane);
        }
#pragma unroll
        for (int v = 0; v < 2; v++) {
            acc[v].x += t0[v].x + t1[v].x;
            acc[v].y += t0[v].y + t1[v].y;
            acc[v].z += t0[v].z + t1[v].z;
            acc[v].w += t0[v].w + t1[v].w;
        }
    }
    if (e < end) {
        const float4* p0 = hv + (size_t)g_col[e] * 64;
#pragma unroll
        for (int v = 0; v < 2; v++) {
            float4 t0 = __ldg(p0 + v * 32 + lane);
            acc[v].x += t0.x; acc[v].y += t0.y; acc[v].z += t0.z; acc[v].w += t0.w;
        }
    }
#pragma unroll
    for (int v = 0; v < 2; v++) {
        uint2 hw = make_uint2(pack_hi(acc[v].x, acc[v].y), pack_hi(acc[v].z, acc[v].w));
        uint2 lw = make_uint2(pack_lo(acc[v].x, acc[v].y), pack_lo(acc[v].z, acc[v].w));
        ((uint2*)OH)[(size_t)w * 64 + v * 32 + lane] = hw;
        ((uint2*)OL)[(size_t)w * 64 + v * 32 + lane] = lw;
    }
}

// ---------------- BN fold ----------------
__global__ void k_bnfold(const float* __restrict__ g, const float* __restrict__ be,
                         const float* __restrict__ mu, const float* __restrict__ var,
                         const float* __restrict__ b1, int off) {
    int j = threadIdx.x;
    float s = g[j] * rsqrtf(var[j] + 1e-5f);
    g_s[off + j] = s;
    g_t[off + j] = (b1[j] - mu[j]) * s + be[j];
}

// ---------------- weight conversions ----------------
__global__ void k_wconv_all(const float* __restrict__ w0, const float* __restrict__ w1,
                            const float* __restrict__ w2, const float* __restrict__ w3,
                            const float* __restrict__ w4) {
    int widx = blockIdx.y;
    int k = blockIdx.x;
    int n = threadIdx.x;
    const float* W;
    int K = 256;
    switch (widx) {
        case 0: W = w0; K = 128; break;
        case 1: W = w1; break;
        case 2: W = w2; break;
        case 3: W = w3; break;
        default: W = w4; break;
    }
    if (k >= K) return;
    float v = W[k * 256 + n];
    __nv_bfloat16 h = __float2bfloat16(v);
    __nv_bfloat16 l = __float2bfloat16(v - __bfloat162float(h));
    size_t o = (size_t)widx * 65536 + k * 256 + n;
    g_wh[o] = h;
    g_wl[o] = l;
}

// ---------------- fused tail weights ----------------
__global__ void k_wc(const float* __restrict__ W2, const float* __restrict__ b2,
                     const float* __restrict__ oW, const float* __restrict__ ob) {
    int i = threadIdx.x;
    float a0 = 0.f, a1 = 0.f;
    for (int d = 0; d < 256; d++) {
        float w = W2[i * 256 + d];
        a0 += w * oW[2 * d];
        a1 += w * oW[2 * d + 1];
    }
    g_wc[2 * i] = a0;
    g_wc[2 * i + 1] = a1;
    if (i < 2) {
        float b = 0.f;
        for (int d = 0; d < 256; d++) b += b2[d] * oW[2 * d + i];
        g_wc[512 + i] = b + ob[i];
    }
}

// ---------------- pure cp.async + wmma split-bf16 GEMM ----------------
// CTA tile 128x128, grid (ceil(M/128), 2), 8 warps 4x2 (warp 32x64), K-chunk 32.
// A given as pre-split bf16 planes. mode 0: relu(v*sc+sh) -> planes; mode 1: relu(v+sh) -> fp32.
#define ALD 40
#define BLD 136
#define A_IMG (128 * ALD * 2)                 // 10240 B per plane image
#define B_IMG (32 * BLD * 2)                  // 8704 B per plane image
#define BUF_BYTES (2 * A_IMG + 2 * B_IMG)     // 37888
#define SM_BYTES (2 * BUF_BYTES)              // 75776 (C tile 69632 overlays)

__global__ __launch_bounds__(256, 2) void k_mgemm(
    const __nv_bfloat16* __restrict__ AH, const __nv_bfloat16* __restrict__ AL,
    float* __restrict__ Cf, __nv_bfloat16* __restrict__ CH, __nv_bfloat16* __restrict__ CL,
    int M, int K, const float* __restrict__ sc, const float* __restrict__ sh,
    int mode, int widx) {
    extern __shared__ char sm[];
    float* Cs = (float*)sm;
    int tid = threadIdx.x, wid = tid >> 5;
    int bm = blockIdx.x, bn = blockIdx.y;
    int moff = (wid & 3) * 32, noff = (wid >> 2) * 64;
    const __nv_bfloat16* WH = g_wh + (size_t)widx * 65536;
    const __nv_bfloat16* WL = g_wl + (size_t)widx * 65536;

    wmma::fragment<wmma::accumulator, 16, 16, 16, float> acc[2][4];
#pragma unroll
    for (int mf = 0; mf < 2; mf++)
#pragma unroll
        for (int nf = 0; nf < 4; nf++) wmma::fill_fragment(acc[mf][nf], 0.0f);

    const int nch = K >> 5;

    auto issueA = [&](int kt, int b) {
        char* SH = sm + b * BUF_BYTES;
        char* SL = SH + A_IMG;
#pragma unroll
        for (int i = 0; i < 2; i++) {
            int j = tid + i * 256;
            int row = j >> 2, c = (j & 3) * 8;
            int rg = bm * 128 + row;
            if (rg < M) {
                size_t go = (size_t)rg * K + kt + c;
                int so = (row * ALD + c) * 2;
                CP16(smem_cast(SH + so), AH + go);
                CP16(smem_cast(SL + so), AL + go);
            }
        }
    };
    auto issueB = [&](int kt, int b) {
        char* BH = sm + b * BUF_BYTES + 2 * A_IMG;
        char* BL = BH + B_IMG;
#pragma unroll
        for (int i = 0; i < 2; i++) {
            int j = tid + i * 256;
            int r = j >> 4, cc = (j & 15) * 8;
            size_t go = (size_t)(kt + r) * 256 + bn * 128 + cc;
            int so = (r * BLD + cc) * 2;
            CP16(smem_cast(BH + so), WH + go);
            CP16(smem_cast(BL + so), WL + go);
        }
    };
    auto compute = [&](int b) {
        const __nv_bfloat16* SAH = (const __nv_bfloat16*)(sm + b * BUF_BYTES);
        const __nv_bfloat16* SAL = SAH + A_IMG / 2;
        const __nv_bfloat16* SBH = (const __nv_bfloat16*)(sm + b * BUF_BYTES + 2 * A_IMG);
        const __nv_bfloat16* SBL = SBH + B_IMG / 2;
#pragma unroll
        for (int kk = 0; kk < 32; kk += 16) {
            wmma::fragment<wmma::matrix_a, 16, 16, 16, __nv_bfloat16, wmma::row_major> ah[2], al2[2];
#pragma unroll
            for (int mf = 0; mf < 2; mf++) {
                wmma::load_matrix_sync(ah[mf], SAH + (moff + mf * 16) * ALD + kk, ALD);
                wmma::load_matrix_sync(al2[mf], SAL + (moff + mf * 16) * ALD + kk, ALD);
            }
#pragma unroll
            for (int nf = 0; nf < 4; nf++) {
                wmma::fragment<wmma::matrix_b, 16, 16, 16, __nv_bfloat16, wmma::row_major> bh, bl;
                wmma::load_matrix_sync(bh, SBH + kk * BLD + noff + nf * 16, BLD);
                wmma::load_matrix_sync(bl, SBL + kk * BLD + noff + nf * 16, BLD);
#pragma unroll
                for (int mf = 0; mf < 2; mf++) {
                    wmma::mma_sync(acc[mf][nf], ah[mf], bh, acc[mf][nf]);
                    wmma::mma_sync(acc[mf][nf], ah[mf], bl, acc[mf][nf]);
                    wmma::mma_sync(acc[mf][nf], al2[mf], bh, acc[mf][nf]);
                }
            }
        }
    };

    issueA(0, 0);
    issueB(0, 0);
    CP_COMMIT();

    for (int kc = 0; kc < nch; kc++) {
        CP_WAIT0();
        __syncthreads();
        if (kc + 1 < nch) {
            issueA((kc + 1) * 32, (kc + 1) & 1);
            issueB((kc + 1) * 32, (kc + 1) & 1);
            CP_COMMIT();
        }
        compute(kc & 1);
    }

    __syncthreads();
#pragma unroll
    for (int mf = 0; mf < 2; mf++)
#pragma unroll
        for (int nf = 0; nf < 4; nf++)
            wmma::store_matrix_sync(Cs + (moff + mf * 16) * BLD + noff + nf * 16,
                                    acc[mf][nf], BLD, wmma::mem_row_major);
    __syncthreads();

    int row = tid >> 1;
    int cs = (tid & 1) * 64;
    int rg = bm * 128 + row;
    if (rg < M) {
#pragma unroll
        for (int q = 0; q < 16; q++) {
            int c = cs + q * 4;
            int gc = bn * 128 + c;
            float4 v = *(float4*)(Cs + row * BLD + c);
            float o[4] = {v.x, v.y, v.z, v.w};
            if (mode == 0) {
#pragma unroll
                for (int j = 0; j < 4; j++)
                    o[j] = fmaxf(o[j] * __ldg(sc + gc + j) + __ldg(sh + gc + j), 0.f);
                uint2 hw = make_uint2(pack_hi(o[0], o[1]), pack_hi(o[2], o[3]));
                uint2 lw = make_uint2(pack_lo(o[0], o[1]), pack_lo(o[2], o[3]));
                *(uint2*)(CH + (size_t)rg * 256 + gc) = hw;
                *(uint2*)(CL + (size_t)rg * 256 + gc) = lw;
            } else {
#pragma unroll
                for (int j = 0; j < 4; j++)
                    o[j] = fmaxf(o[j] + __ldg(sh + gc + j), 0.f);
                *(float4*)(Cf + (size_t)rg * 256 + gc) = make_float4(o[0], o[1], o[2], o[3]);
            }
        }
    }
}

// ---------------- final projection (planar in): out = (hi+lo) @ Wc + bc ----------------
__global__ void k_out(const __nv_bfloat16* __restrict__ HH, const __nv_bfloat16* __restrict__ HL,
                      const float* __restrict__ W, const float* __restrict__ b,
                      float* __restrict__ out) {
    __shared__ float Ws[512];
    int tid = threadIdx.x;
    Ws[tid] = W[tid];
    Ws[tid + 256] = W[tid + 256];
    __syncthreads();
    int w = (blockIdx.x * blockDim.x + tid) >> 5;
    if (w >= NN) return;
    int lane = tid & 31;
    uint4 h4 = __ldg((const uint4*)HH + (size_t)w * 32 + lane);
    uint4 l4 = __ldg((const uint4*)HL + (size_t)w * 32 + lane);
    uint32_t hw[4] = {h4.x, h4.y, h4.z, h4.w};
    uint32_t lw[4] = {l4.x, l4.y, l4.z, l4.w};
    float a0 = 0.f, a1 = 0.f;
    int kb = lane * 8;
#pragma unroll
    for (int q = 0; q < 4; q++) {
        float v0 = blo(hw[q]) + blo(lw[q]);
        float v1 = bhi(hw[q]) + bhi(lw[q]);
        int k = kb + 2 * q;
        a0 += v0 * Ws[2 * k] + v1 * Ws[2 * k + 2];
        a1 += v0 * Ws[2 * k + 1] + v1 * Ws[2 * k + 3];
    }
#pragma unroll
    for (int off = 16; off > 0; off >>= 1) {
        a0 += __shfl_down_sync(0xffffffffu, a0, off);
        a1 += __shfl_down_sync(0xffffffffu, a1, off);
    }
    if (lane == 0) {
        out[(size_t)w * 2 + 0] = a0 + b[0];
        out[(size_t)w * 2 + 1] = a1 + b[1];
    }
}

// ---------------- host ----------------
extern "C" void kernel_launch(void* const* d_in, const int* in_sizes, int n_in,
                              void* d_out, int out_size) {
    const float* x = (const float*)d_in[0];
    const int* ei = (const int*)d_in[1];
    const float* outW = (const float*)d_in[26];
    const float* outB = (const float*)d_in[27];
    auto L = [&](int l, int p) { return (const float*)d_in[2 + l * 8 + p]; };

    float *z0, *z1, *hb, *sp, *tp, *wc;
    int* cur;
    cudaGetSymbolAddress((void**)&z0, g_z0);
    cudaGetSymbolAddress((void**)&z1, g_z1);
    cudaGetSymbolAddress((void**)&hb, g_hb);
    cudaGetSymbolAddress((void**)&sp, g_s);
    cudaGetSymbolAddress((void**)&tp, g_t);
    cudaGetSymbolAddress((void**)&wc, g_wc);
    cudaGetSymbolAddress((void**)&cur, g_cursor);

    __nv_bfloat16* z0H = (__nv_bfloat16*)z0;
    __nv_bfloat16* z1H = (__nv_bfloat16*)z1;
    __nv_bfloat16* z0L128 = z0H + (size_t)NN * 128;
    __nv_bfloat16* z0L = z0H + (size_t)NN * 256;
    __nv_bfloat16* z1L = z1H + (size_t)NN * 256;

    cudaFuncSetAttribute(k_mgemm, cudaFuncAttributeMaxDynamicSharedMemorySize, SM_BYTES);

    // ---- CSR build ----
    cudaMemsetAsync(cur, 0, NN * sizeof(int));
    k_count<<<(NE + 255) / 256, 256>>>(ei + NE);
    k_scan<<<1, 1024>>>();
    k_fill<<<(NE + 255) / 256, 256>>>(ei);

    int aggBlocks = (NN + 7) / 8;
    dim3 gg((NN + 127) / 128, 2);

    // layer-1 aggregation + parameter prep
    k_agg1<<<aggBlocks, 256>>>(x, z0H, z0L128);
    k_wconv_all<<<dim3(256, 5), 256>>>(L(0, 0), L(0, 6), L(1, 0), L(1, 6), L(2, 0));
    k_bnfold<<<1, 256>>>(L(0, 2), L(0, 3), L(0, 4), L(0, 5), L(0, 1), 0);
    k_bnfold<<<1, 256>>>(L(1, 2), L(1, 3), L(1, 4), L(1, 5), L(1, 1), 256);
    k_bnfold<<<1, 256>>>(L(2, 2), L(2, 3), L(2, 4), L(2, 5), L(2, 1), 512);
    k_wc<<<1, 256>>>(L(2, 6), L(2, 7), outW, outB);

    // Layer 1
    k_mgemm<<<gg, 256, SM_BYTES>>>(z0H, z0L128, nullptr, z1H, z1L, NN, 128, sp, tp, 0, 0);
    k_mgemm<<<gg, 256, SM_BYTES>>>(z1H, z1L, hb, nullptr, nullptr, NN, 256, nullptr, L(0, 7), 1, 1);

    // Layer 2
    k_agg2<<<aggBlocks, 256>>>(hb, z0H, z0L);
    k_mgemm<<<gg, 256, SM_BYTES>>>(z0H, z0L, nullptr, z1H, z1L, NN, 256, sp + 256, tp + 256, 0, 2);
    k_mgemm<<<gg, 256, SM_BYTES>>>(z1H, z1L, hb, nullptr, nullptr, NN, 256, nullptr, L(1, 7), 1, 3);

    // Layer 3 first GEMM (planes out), then fused tail
    k_agg2<<<aggBlocks, 256>>>(hb, z0H, z0L);
    k_mgemm<<<gg, 256, SM_BYTES>>>(z0H, z0L, nullptr, z1H, z1L, NN, 256, sp + 512, tp + 512, 0, 4);
    k_out<<<aggBlocks, 256>>>(z1H, z1L, wc, wc + 512, (float*)d_out);
}